// round 10
// baseline (speedup 1.0000x reference)
#include <cuda_runtime.h>
#include <math_constants.h>
#include <cstdint>

// Problem constants
#define NN      50000
#define EE      800000
#define FIN     256
#define HH      4
#define DD      32
#define HD      128     // HH*DD
#define NEG_SLOPE 0.2f
#define BUCKET  64      // per-dst edge slot capacity (P(deg>64) ~ e^-50)

typedef unsigned int u32;
typedef unsigned long long u64;

// -------- scratch (no allocations allowed) --------
// g_cnt INVARIANT: zero before every kernel_launch. Zero-initialized at load;
// gat_kernel restores each entry to 0 after consuming it.
__device__ float g_ft[NN * HD];          // projected features fp32 [N, H*D]
__device__ float g_el[NN * HH];          // left logits  [N, H]
__device__ float g_er[NN * HH];          // right logits [N, H]
__device__ int   g_cnt[NN];              // per-dst degree counter
__device__ int   g_esrc[NN * BUCKET];    // src node per edge, bucketed by dst

// ============================================================
// helpers
// ============================================================
__device__ __forceinline__ float to_tf32(float x) {
    u32 o;
    asm("cvt.rna.tf32.f32 %0, %1;" : "=r"(o) : "f"(x));
    return __uint_as_float(o);
}

__device__ __forceinline__ void mma_tf32(float* d, const u32* a,
                                         u32 b0, u32 b1) {
    asm volatile(
        "mma.sync.aligned.m16n8k8.row.col.f32.tf32.tf32.f32 "
        "{%0,%1,%2,%3}, {%4,%5,%6,%7}, {%8,%9}, {%0,%1,%2,%3};\n"
        : "+f"(d[0]), "+f"(d[1]), "+f"(d[2]), "+f"(d[3])
        : "r"(a[0]), "r"(a[1]), "r"(a[2]), "r"(a[3]), "r"(b0), "r"(b1));
}

__device__ __forceinline__ void cp16(void* s, const void* g, bool pred) {
    u32 sa = (u32)__cvta_generic_to_shared(s);
    int sz = pred ? 16 : 0;
    asm volatile("cp.async.cg.shared.global [%0], [%1], 16, %2;\n"
                 :: "r"(sa), "l"(g), "r"(sz));
}
__device__ __forceinline__ void cp_commit() {
    asm volatile("cp.async.commit_group;\n" ::: "memory");
}

// ============================================================
// 1. GEMM: ft[N,128] = feat[N,256] @ W[256,128]  (tf32 tensor core)
//    cp.async 2-stage; tiles converted to tf32 IN SMEM once per stage,
//    so the mma loop is pure LDS->MMA (no CVT on the critical path).
//    Epilogue: fp32 ft store + fused fp32 el/er logits.
// ============================================================
#define A_PITCH 36
#define B_PITCH 132
#define A_TILE  (128 * A_PITCH)
#define B_TILE  (32 * B_PITCH)
#define GEMM_SMEM_BYTES ((2 * A_TILE + 2 * B_TILE) * 4)

__global__ __launch_bounds__(256) void gemm_tc(
    const float* __restrict__ feat, const float* __restrict__ W,
    const float* __restrict__ attn_l, const float* __restrict__ attn_r)
{
    extern __shared__ float sm[];
    float* As = sm;                 // [2][128][A_PITCH]
    float* Bs = sm + 2 * A_TILE;    // [2][32][B_PITCH]

    const int tid  = threadIdx.x;
    const int lane = tid & 31;
    const int warp = tid >> 5;
    const int wm = (warp >> 1) * 32;
    const int wn = (warp & 1) * 64;
    const int g  = lane >> 2;
    const int tg = lane & 3;
    const int row0 = blockIdx.x * 128;

    float acc[2][8][4];
#pragma unroll
    for (int mi = 0; mi < 2; mi++)
#pragma unroll
        for (int ni = 0; ni < 8; ni++)
#pragma unroll
            for (int j = 0; j < 4; j++) acc[mi][ni][j] = 0.f;

    auto load_tile = [&](int stage, int k0) {
        float* A = As + stage * A_TILE;
        float* B = Bs + stage * B_TILE;
#pragma unroll
        for (int i = 0; i < 4; i++) {
            int idx = tid + i * 256;
            int r = idx >> 3, c = (idx & 7) * 4;
            bool p = (row0 + r) < NN;
            cp16(&A[r * A_PITCH + c], &feat[(size_t)(row0 + r) * FIN + k0 + c], p);
        }
#pragma unroll
        for (int i = 0; i < 4; i++) {
            int idx = tid + i * 256;
            int r = idx >> 5, c = (idx & 31) * 4;
            cp16(&B[r * B_PITCH + c], &W[(k0 + r) * HD + c], true);
        }
        cp_commit();
    };

    load_tile(0, 0);

    for (int kt = 0; kt < 8; kt++) {
        int cur = kt & 1;
        if (kt < 7) {
            load_tile(cur ^ 1, (kt + 1) * 32);
            asm volatile("cp.async.wait_group %0;\n" :: "n"(1) : "memory");
        } else {
            asm volatile("cp.async.wait_group %0;\n" :: "n"(0) : "memory");
        }
        __syncthreads();

        float* A = As + cur * A_TILE;
        float* B = Bs + cur * B_TILE;

        // ---- in-place tf32 conversion of the ready stage ----
#pragma unroll
        for (int i = 0; i < 4; i++) {
            int idx = tid + i * 256;
            int r = idx >> 3, c = (idx & 7) * 4;
            float4* pa = (float4*)&A[r * A_PITCH + c];
            float4 v = *pa;
            v.x = to_tf32(v.x); v.y = to_tf32(v.y);
            v.z = to_tf32(v.z); v.w = to_tf32(v.w);
            *pa = v;
        }
#pragma unroll
        for (int i = 0; i < 4; i++) {
            int idx = tid + i * 256;
            int r = idx >> 5, c = (idx & 31) * 4;
            float4* pb = (float4*)&B[r * B_PITCH + c];
            float4 v = *pb;
            v.x = to_tf32(v.x); v.y = to_tf32(v.y);
            v.z = to_tf32(v.z); v.w = to_tf32(v.w);
            *pb = v;
        }
        __syncthreads();

#pragma unroll
        for (int kf = 0; kf < 4; kf++) {
            int kb = kf * 8;
            u32 a[2][4];
#pragma unroll
            for (int mi = 0; mi < 2; mi++) {
                int rb = wm + mi * 16;
                a[mi][0] = __float_as_uint(A[(rb + g    ) * A_PITCH + kb + tg    ]);
                a[mi][1] = __float_as_uint(A[(rb + g + 8) * A_PITCH + kb + tg    ]);
                a[mi][2] = __float_as_uint(A[(rb + g    ) * A_PITCH + kb + tg + 4]);
                a[mi][3] = __float_as_uint(A[(rb + g + 8) * A_PITCH + kb + tg + 4]);
            }
#pragma unroll
            for (int ni = 0; ni < 8; ni++) {
                u32 b0 = __float_as_uint(B[(kb + tg    ) * B_PITCH + wn + ni * 8 + g]);
                u32 b1 = __float_as_uint(B[(kb + tg + 4) * B_PITCH + wn + ni * 8 + g]);
                mma_tf32(acc[0][ni], a[0], b0, b1);
                mma_tf32(acc[1][ni], a[1], b0, b1);
            }
        }
        __syncthreads();
    }

    // ---- epilogue part 1: fp32 ft store ----
#pragma unroll
    for (int mi = 0; mi < 2; mi++) {
        int r = row0 + wm + mi * 16 + g;
#pragma unroll
        for (int ni = 0; ni < 8; ni++) {
            int c = wn + ni * 8 + 2 * tg;
            if (r < NN)
                *(float2*)&g_ft[(size_t)r * HD + c] = make_float2(acc[mi][ni][0], acc[mi][ni][1]);
            if (r + 8 < NN)
                *(float2*)&g_ft[(size_t)(r + 8) * HD + c] = make_float2(acc[mi][ni][2], acc[mi][ni][3]);
        }
    }

    // ---- epilogue part 2: fused fp32 logits ----
    float alv[8][2], arv[8][2];
#pragma unroll
    for (int ni = 0; ni < 8; ni++) {
        int c = wn + ni * 8 + 2 * tg;
        alv[ni][0] = attn_l[c];     alv[ni][1] = attn_l[c + 1];
        arv[ni][0] = attn_r[c];     arv[ni][1] = attn_r[c + 1];
    }
#pragma unroll
    for (int mi = 0; mi < 2; mi++) {
        int r = row0 + wm + mi * 16 + g;
#pragma unroll
        for (int half = 0; half < 2; half++) {
            float el_lo = 0.f, er_lo = 0.f, el_hi = 0.f, er_hi = 0.f;
#pragma unroll
            for (int k = 0; k < 4; k++) {
                int ni = half * 4 + k;
                el_lo += acc[mi][ni][0] * alv[ni][0] + acc[mi][ni][1] * alv[ni][1];
                er_lo += acc[mi][ni][0] * arv[ni][0] + acc[mi][ni][1] * arv[ni][1];
                el_hi += acc[mi][ni][2] * alv[ni][0] + acc[mi][ni][3] * alv[ni][1];
                er_hi += acc[mi][ni][2] * arv[ni][0] + acc[mi][ni][3] * arv[ni][1];
            }
#pragma unroll
            for (int off = 1; off < 4; off <<= 1) {
                el_lo += __shfl_xor_sync(0xffffffffu, el_lo, off);
                er_lo += __shfl_xor_sync(0xffffffffu, er_lo, off);
                el_hi += __shfl_xor_sync(0xffffffffu, el_hi, off);
                er_hi += __shfl_xor_sync(0xffffffffu, er_hi, off);
            }
            if (tg == 0) {
                int h = (wn >> 5) + half;
                if (r < NN) {
                    g_el[r * HH + h] = el_lo;
                    g_er[r * HH + h] = er_lo;
                }
                if (r + 8 < NN) {
                    g_el[(r + 8) * HH + h] = el_hi;
                    g_er[(r + 8) * HH + h] = er_hi;
                }
            }
        }
    }
}

// ============================================================
// 2. bucketed edge scatter (g_cnt zeroed by previous gat / initial BSS)
// ============================================================
__global__ void scatter_kernel(const int* __restrict__ src, const int* __restrict__ dst)
{
    int e = blockIdx.x * blockDim.x + threadIdx.x;
    if (e >= EE) return;
    int s = __ldg(&src[e]);
    int d = __ldg(&dst[e]);
    int p = atomicAdd(&g_cnt[d], 1);
    if (p < BUCKET) g_esrc[d * BUCKET + p] = s;
}

// ============================================================
// 3. warp-per-dst-node GAT: two-phase softmax; pass B = R8 form
//    (unroll-4 implicit pipeline — 8-deep batching spilled registers).
// ============================================================
__device__ __forceinline__ float leaky(float x) {
    return (x > 0.f) ? x : NEG_SLOPE * x;
}

__global__ __launch_bounds__(256) void gat_kernel(
    const float* __restrict__ bias, float* __restrict__ out)
{
    __shared__ float2 swe[8][HH][BUCKET];   // 16 KB

    int v = (blockIdx.x * blockDim.x + threadIdx.x) >> 5;
    int lane = threadIdx.x & 31;
    int wrp  = threadIdx.x >> 5;
    if (v >= NN) return;
    float2 (*we)[BUCKET] = swe[wrp];

    int deg = min(g_cnt[v], BUCKET);
    if (lane == 0) g_cnt[v] = 0;     // restore zero-invariant for next replay

    float4 b = *(const float4*)&bias[lane * 4];

    if (deg == 0) {
        *(float4*)&out[(size_t)v * HD + lane * 4] = b;
        return;
    }
    int beg = v * BUCKET;

    float4 er4 = *(const float4*)&g_er[v * HH];

    // ---- pass A: stage {u, leaky logit} per (edge, head); per-head max ----
    float m[4] = { -CUDART_INF_F, -CUDART_INF_F, -CUDART_INF_F, -CUDART_INF_F };

    for (int i = lane; i < deg; i += 32) {
        int u = g_esrc[beg + i];
        float4 el4 = *(const float4*)&g_el[u * HH];
        float ub = __int_as_float(u);
        float x0 = leaky(el4.x + er4.x);
        float x1 = leaky(el4.y + er4.y);
        float x2 = leaky(el4.z + er4.z);
        float x3 = leaky(el4.w + er4.w);
        we[0][i] = make_float2(ub, x0);
        we[1][i] = make_float2(ub, x1);
        we[2][i] = make_float2(ub, x2);
        we[3][i] = make_float2(ub, x3);
        m[0] = fmaxf(m[0], x0);
        m[1] = fmaxf(m[1], x1);
        m[2] = fmaxf(m[2], x2);
        m[3] = fmaxf(m[3], x3);
    }

    // ---- warp max merge ----
#pragma unroll
    for (int off = 16; off; off >>= 1) {
#pragma unroll
        for (int h = 0; h < 4; h++)
            m[h] = fmaxf(m[h], __shfl_xor_sync(0xffffffffu, m[h], off));
    }
    __syncwarp();

    // ---- weight phase (head-major): e = exp(x - m[h]); 8-lane group sums ----
    int h  = lane >> 3;
    int i0 = lane & 7;
    float mh = m[h];
    float sloc = 0.f;
    for (int i = i0; i < deg; i += 8) {
        float x = we[h][i].y;
        float a = __expf(x - mh);
        we[h][i].y = a;
        sloc += a;
    }
#pragma unroll
    for (int off = 1; off < 8; off <<= 1)
        sloc += __shfl_xor_sync(0xffffffffu, sloc, off);
    float inv = 1.f / sloc;
    __syncwarp();

    // ---- pass B: aggregate (unnormalized), lane owns dims [lane*4, lane*4+4) ----
    u64 accA = 0ull, accB = 0ull;
    const char* ftbase = (const char*)g_ft + (size_t)lane * 16;

#pragma unroll 4
    for (int i = 0; i < deg; i++) {
        float2 p = we[h][i];                    // one LDS.64, broadcast
        int u = __float_as_int(p.x);
        u64 aa;
        asm("mov.b64 %0, {%1, %1};" : "=l"(aa) : "r"(__float_as_uint(p.y)));
        ulonglong2 f = *(const ulonglong2*)(ftbase + (size_t)u * (HD * 4)); // LDG.128
        asm("fma.rn.f32x2 %0, %1, %2, %0;" : "+l"(accA) : "l"(f.x), "l"(aa));
        asm("fma.rn.f32x2 %0, %1, %2, %0;" : "+l"(accB) : "l"(f.y), "l"(aa));
    }

    u32 a0, a1, a2, a3;
    asm("mov.b64 {%0, %1}, %2;" : "=r"(a0), "=r"(a1) : "l"(accA));
    asm("mov.b64 {%0, %1}, %2;" : "=r"(a2), "=r"(a3) : "l"(accB));
    float4 r;
    r.x = fmaf(__uint_as_float(a0), inv, b.x);
    r.y = fmaf(__uint_as_float(a1), inv, b.y);
    r.z = fmaf(__uint_as_float(a2), inv, b.z);
    r.w = fmaf(__uint_as_float(a3), inv, b.w);
    *(float4*)&out[(size_t)v * HD + lane * 4] = r;
}

// ============================================================
extern "C" void kernel_launch(void* const* d_in, const int* in_sizes, int n_in,
                              void* d_out, int out_size)
{
    const float* feat   = (const float*)d_in[0];
    const int*   src    = (const int*)  d_in[1];
    const int*   dst    = (const int*)  d_in[2];
    const float* W      = (const float*)d_in[3];
    const float* attn_l = (const float*)d_in[4];
    const float* attn_r = (const float*)d_in[5];
    const float* bias   = (const float*)d_in[6];
    float* out = (float*)d_out;

    cudaFuncSetAttribute(gemm_tc, cudaFuncAttributeMaxDynamicSharedMemorySize,
                         GEMM_SMEM_BYTES);

    // projection + fused fp32 logits (tf32 tensor core, cp.async pipelined)
    gemm_tc<<<(NN + 127) / 128, 256, GEMM_SMEM_BYTES>>>(feat, W, attn_l, attn_r);

    // bucketed CSR build (g_cnt zero-invariant maintained by gat_kernel)
    scatter_kernel<<<(EE + 255) / 256, 256>>>(src, dst);

    // softmax + SpMM
    gat_kernel<<<(NN * 32 + 255) / 256, 256>>>(bias, out);
}

// round 11
// speedup vs baseline: 1.0062x; 1.0062x over previous
#include <cuda_runtime.h>
#include <math_constants.h>
#include <cstdint>

// Problem constants
#define NN      50000
#define EE      800000
#define FIN     256
#define HH      4
#define DD      32
#define HD      128     // HH*DD
#define NEG_SLOPE 0.2f
#define BUCKET  64      // per-dst edge slot capacity (P(deg>64) ~ e^-50)

typedef unsigned int u32;
typedef unsigned long long u64;

// -------- scratch (no allocations allowed) --------
// g_cnt INVARIANT: zero before every kernel_launch. Zero-initialized at load;
// gat_kernel restores each entry to 0 after consuming it.
__device__ float g_ft[NN * HD];          // projected features fp32 [N, H*D]
__device__ float g_el[NN * HH];          // left logits  [N, H]
__device__ float g_er[NN * HH];          // right logits [N, H]
__device__ int   g_cnt[NN];              // per-dst degree counter
__device__ int   g_esrc[NN * BUCKET];    // src node per edge, bucketed by dst

// ============================================================
// helpers
// ============================================================
__device__ __forceinline__ float to_tf32(float x) {
    u32 o;
    asm("cvt.rna.tf32.f32 %0, %1;" : "=r"(o) : "f"(x));
    return __uint_as_float(o);
}

__device__ __forceinline__ void mma_tf32(float* d, const u32* a,
                                         u32 b0, u32 b1) {
    asm volatile(
        "mma.sync.aligned.m16n8k8.row.col.f32.tf32.tf32.f32 "
        "{%0,%1,%2,%3}, {%4,%5,%6,%7}, {%8,%9}, {%0,%1,%2,%3};\n"
        : "+f"(d[0]), "+f"(d[1]), "+f"(d[2]), "+f"(d[3])
        : "r"(a[0]), "r"(a[1]), "r"(a[2]), "r"(a[3]), "r"(b0), "r"(b1));
}

__device__ __forceinline__ void cp16(void* s, const void* g, bool pred) {
    u32 sa = (u32)__cvta_generic_to_shared(s);
    int sz = pred ? 16 : 0;
    asm volatile("cp.async.cg.shared.global [%0], [%1], 16, %2;\n"
                 :: "r"(sa), "l"(g), "r"(sz));
}
__device__ __forceinline__ void cp_commit() {
    asm volatile("cp.async.commit_group;\n" ::: "memory");
}

// ============================================================
// 1. GEMM: ft[N,128] = feat[N,256] @ W[256,128]  (tf32 tensor core)
//    BM=64, BN=128, BK=32, 8 warps (2M x 4N), warp tile 32x32.
//    52 KB smem -> 2 CTAs/SM. cp.async 2-stage pipeline.
//    Epilogue: fp32 ft store + fused fp32 el/er logits (1 head per warp).
// ============================================================
#define A_PITCH 36
#define B_PITCH 132
#define A_TILE  (64 * A_PITCH)
#define B_TILE  (32 * B_PITCH)
#define GEMM_SMEM_BYTES ((2 * A_TILE + 2 * B_TILE) * 4)

__global__ __launch_bounds__(256, 2) void gemm_tc(
    const float* __restrict__ feat, const float* __restrict__ W,
    const float* __restrict__ attn_l, const float* __restrict__ attn_r)
{
    extern __shared__ float sm[];
    float* As = sm;                 // [2][64][A_PITCH]
    float* Bs = sm + 2 * A_TILE;    // [2][32][B_PITCH]

    const int tid  = threadIdx.x;
    const int lane = tid & 31;
    const int warp = tid >> 5;
    const int wm = (warp >> 2) * 32;   // 2 M groups
    const int wn = (warp & 3) * 32;    // 4 N groups -> head = warp & 3
    const int g  = lane >> 2;
    const int tg = lane & 3;
    const int row0 = blockIdx.x * 64;

    float acc[2][4][4];
#pragma unroll
    for (int mi = 0; mi < 2; mi++)
#pragma unroll
        for (int ni = 0; ni < 4; ni++)
#pragma unroll
            for (int j = 0; j < 4; j++) acc[mi][ni][j] = 0.f;

    auto load_tile = [&](int stage, int k0) {
        float* A = As + stage * A_TILE;
        float* B = Bs + stage * B_TILE;
#pragma unroll
        for (int i = 0; i < 2; i++) {       // A: 64x32 = 512 float4
            int idx = tid + i * 256;
            int r = idx >> 3, c = (idx & 7) * 4;
            bool p = (row0 + r) < NN;
            cp16(&A[r * A_PITCH + c], &feat[(size_t)(row0 + r) * FIN + k0 + c], p);
        }
#pragma unroll
        for (int i = 0; i < 4; i++) {       // B: 32x128 = 1024 float4
            int idx = tid + i * 256;
            int r = idx >> 5, c = (idx & 31) * 4;
            cp16(&B[r * B_PITCH + c], &W[(k0 + r) * HD + c], true);
        }
        cp_commit();
    };

    load_tile(0, 0);

    for (int kt = 0; kt < 8; kt++) {
        int cur = kt & 1;
        if (kt < 7) {
            load_tile(cur ^ 1, (kt + 1) * 32);
            asm volatile("cp.async.wait_group %0;\n" :: "n"(1) : "memory");
        } else {
            asm volatile("cp.async.wait_group %0;\n" :: "n"(0) : "memory");
        }
        __syncthreads();

        const float* A = As + cur * A_TILE;
        const float* B = Bs + cur * B_TILE;
#pragma unroll
        for (int kf = 0; kf < 4; kf++) {
            int kb = kf * 8;
            u32 a[2][4];
#pragma unroll
            for (int mi = 0; mi < 2; mi++) {
                int rb = wm + mi * 16;
                a[mi][0] = __float_as_uint(to_tf32(A[(rb + g    ) * A_PITCH + kb + tg    ]));
                a[mi][1] = __float_as_uint(to_tf32(A[(rb + g + 8) * A_PITCH + kb + tg    ]));
                a[mi][2] = __float_as_uint(to_tf32(A[(rb + g    ) * A_PITCH + kb + tg + 4]));
                a[mi][3] = __float_as_uint(to_tf32(A[(rb + g + 8) * A_PITCH + kb + tg + 4]));
            }
#pragma unroll
            for (int ni = 0; ni < 4; ni++) {
                u32 b0 = __float_as_uint(to_tf32(B[(kb + tg    ) * B_PITCH + wn + ni * 8 + g]));
                u32 b1 = __float_as_uint(to_tf32(B[(kb + tg + 4) * B_PITCH + wn + ni * 8 + g]));
                mma_tf32(acc[0][ni], a[0], b0, b1);
                mma_tf32(acc[1][ni], a[1], b0, b1);
            }
        }
        __syncthreads();
    }

    // ---- epilogue part 1: fp32 ft store ----
#pragma unroll
    for (int mi = 0; mi < 2; mi++) {
        int r = row0 + wm + mi * 16 + g;
#pragma unroll
        for (int ni = 0; ni < 4; ni++) {
            int c = wn + ni * 8 + 2 * tg;
            if (r < NN)
                *(float2*)&g_ft[(size_t)r * HD + c] = make_float2(acc[mi][ni][0], acc[mi][ni][1]);
            if (r + 8 < NN)
                *(float2*)&g_ft[(size_t)(r + 8) * HD + c] = make_float2(acc[mi][ni][2], acc[mi][ni][3]);
        }
    }

    // ---- epilogue part 2: fused fp32 logits (this warp owns head h = warp&3) ----
    const int h = warp & 3;
    float alv[4][2], arv[4][2];
#pragma unroll
    for (int ni = 0; ni < 4; ni++) {
        int c = wn + ni * 8 + 2 * tg;
        alv[ni][0] = attn_l[c];     alv[ni][1] = attn_l[c + 1];
        arv[ni][0] = attn_r[c];     arv[ni][1] = attn_r[c + 1];
    }
#pragma unroll
    for (int mi = 0; mi < 2; mi++) {
        int r = row0 + wm + mi * 16 + g;
        float el_lo = 0.f, er_lo = 0.f, el_hi = 0.f, er_hi = 0.f;
#pragma unroll
        for (int ni = 0; ni < 4; ni++) {
            el_lo += acc[mi][ni][0] * alv[ni][0] + acc[mi][ni][1] * alv[ni][1];
            er_lo += acc[mi][ni][0] * arv[ni][0] + acc[mi][ni][1] * arv[ni][1];
            el_hi += acc[mi][ni][2] * alv[ni][0] + acc[mi][ni][3] * alv[ni][1];
            er_hi += acc[mi][ni][2] * arv[ni][0] + acc[mi][ni][3] * arv[ni][1];
        }
#pragma unroll
        for (int off = 1; off < 4; off <<= 1) {
            el_lo += __shfl_xor_sync(0xffffffffu, el_lo, off);
            er_lo += __shfl_xor_sync(0xffffffffu, er_lo, off);
            el_hi += __shfl_xor_sync(0xffffffffu, el_hi, off);
            er_hi += __shfl_xor_sync(0xffffffffu, er_hi, off);
        }
        if (tg == 0) {
            if (r < NN) {
                g_el[r * HH + h] = el_lo;
                g_er[r * HH + h] = er_lo;
            }
            if (r + 8 < NN) {
                g_el[(r + 8) * HH + h] = el_hi;
                g_er[(r + 8) * HH + h] = er_hi;
            }
        }
    }
}

// ============================================================
// 2. bucketed edge scatter (g_cnt zeroed by previous gat / initial BSS)
// ============================================================
__global__ void scatter_kernel(const int* __restrict__ src, const int* __restrict__ dst)
{
    int e = blockIdx.x * blockDim.x + threadIdx.x;
    if (e >= EE) return;
    int s = __ldg(&src[e]);
    int d = __ldg(&dst[e]);
    int p = atomicAdd(&g_cnt[d], 1);
    if (p < BUCKET) g_esrc[d * BUCKET + p] = s;
}

// ============================================================
// 3. warp-per-dst-node GAT: two-phase softmax; R8 pass B (measured 51 us).
// ============================================================
__device__ __forceinline__ float leaky(float x) {
    return (x > 0.f) ? x : NEG_SLOPE * x;
}

__global__ __launch_bounds__(256) void gat_kernel(
    const float* __restrict__ bias, float* __restrict__ out)
{
    __shared__ float2 swe[8][HH][BUCKET];   // 16 KB

    int v = (blockIdx.x * blockDim.x + threadIdx.x) >> 5;
    int lane = threadIdx.x & 31;
    int wrp  = threadIdx.x >> 5;
    if (v >= NN) return;
    float2 (*we)[BUCKET] = swe[wrp];

    int deg = min(g_cnt[v], BUCKET);
    if (lane == 0) g_cnt[v] = 0;     // restore zero-invariant for next replay

    float4 b = *(const float4*)&bias[lane * 4];

    if (deg == 0) {
        *(float4*)&out[(size_t)v * HD + lane * 4] = b;
        return;
    }
    int beg = v * BUCKET;

    float4 er4 = *(const float4*)&g_er[v * HH];

    // ---- pass A: stage {u, leaky logit} per (edge, head); per-head max ----
    float m[4] = { -CUDART_INF_F, -CUDART_INF_F, -CUDART_INF_F, -CUDART_INF_F };

    for (int i = lane; i < deg; i += 32) {
        int u = g_esrc[beg + i];
        float4 el4 = *(const float4*)&g_el[u * HH];
        float ub = __int_as_float(u);
        float x0 = leaky(el4.x + er4.x);
        float x1 = leaky(el4.y + er4.y);
        float x2 = leaky(el4.z + er4.z);
        float x3 = leaky(el4.w + er4.w);
        we[0][i] = make_float2(ub, x0);
        we[1][i] = make_float2(ub, x1);
        we[2][i] = make_float2(ub, x2);
        we[3][i] = make_float2(ub, x3);
        m[0] = fmaxf(m[0], x0);
        m[1] = fmaxf(m[1], x1);
        m[2] = fmaxf(m[2], x2);
        m[3] = fmaxf(m[3], x3);
    }

    // ---- warp max merge ----
#pragma unroll
    for (int off = 16; off; off >>= 1) {
#pragma unroll
        for (int h = 0; h < 4; h++)
            m[h] = fmaxf(m[h], __shfl_xor_sync(0xffffffffu, m[h], off));
    }
    __syncwarp();

    // ---- weight phase (head-major): e = exp(x - m[h]); 8-lane group sums ----
    int h  = lane >> 3;
    int i0 = lane & 7;
    float mh = m[h];
    float sloc = 0.f;
    for (int i = i0; i < deg; i += 8) {
        float x = we[h][i].y;
        float a = __expf(x - mh);
        we[h][i].y = a;
        sloc += a;
    }
#pragma unroll
    for (int off = 1; off < 8; off <<= 1)
        sloc += __shfl_xor_sync(0xffffffffu, sloc, off);
    float inv = 1.f / sloc;
    __syncwarp();

    // ---- pass B: aggregate (unnormalized), lane owns dims [lane*4, lane*4+4) ----
    u64 accA = 0ull, accB = 0ull;
    const char* ftbase = (const char*)g_ft + (size_t)lane * 16;

#pragma unroll 4
    for (int i = 0; i < deg; i++) {
        float2 p = we[h][i];                    // one LDS.64, broadcast
        int u = __float_as_int(p.x);
        u64 aa;
        asm("mov.b64 %0, {%1, %1};" : "=l"(aa) : "r"(__float_as_uint(p.y)));
        ulonglong2 f = *(const ulonglong2*)(ftbase + (size_t)u * (HD * 4)); // LDG.128
        asm("fma.rn.f32x2 %0, %1, %2, %0;" : "+l"(accA) : "l"(f.x), "l"(aa));
        asm("fma.rn.f32x2 %0, %1, %2, %0;" : "+l"(accB) : "l"(f.y), "l"(aa));
    }

    u32 a0, a1, a2, a3;
    asm("mov.b64 {%0, %1}, %2;" : "=r"(a0), "=r"(a1) : "l"(accA));
    asm("mov.b64 {%0, %1}, %2;" : "=r"(a2), "=r"(a3) : "l"(accB));
    float4 r;
    r.x = fmaf(__uint_as_float(a0), inv, b.x);
    r.y = fmaf(__uint_as_float(a1), inv, b.y);
    r.z = fmaf(__uint_as_float(a2), inv, b.z);
    r.w = fmaf(__uint_as_float(a3), inv, b.w);
    *(float4*)&out[(size_t)v * HD + lane * 4] = r;
}

// ============================================================
extern "C" void kernel_launch(void* const* d_in, const int* in_sizes, int n_in,
                              void* d_out, int out_size)
{
    const float* feat   = (const float*)d_in[0];
    const int*   src    = (const int*)  d_in[1];
    const int*   dst    = (const int*)  d_in[2];
    const float* W      = (const float*)d_in[3];
    const float* attn_l = (const float*)d_in[4];
    const float* attn_r = (const float*)d_in[5];
    const float* bias   = (const float*)d_in[6];
    float* out = (float*)d_out;

    cudaFuncSetAttribute(gemm_tc, cudaFuncAttributeMaxDynamicSharedMemorySize,
                         GEMM_SMEM_BYTES);

    // projection + fused fp32 logits (tf32 tensor core, 2 CTAs/SM)
    gemm_tc<<<(NN + 63) / 64, 256, GEMM_SMEM_BYTES>>>(feat, W, attn_l, attn_r);

    // bucketed CSR build (g_cnt zero-invariant maintained by gat_kernel)
    scatter_kernel<<<(EE + 255) / 256, 256>>>(src, dst);

    // softmax + SpMM
    gat_kernel<<<(NN * 32 + 255) / 256, 256>>>(bias, out);
}

// round 12
// speedup vs baseline: 1.3397x; 1.3315x over previous
#include <cuda_runtime.h>
#include <math_constants.h>
#include <cstdint>

// Problem constants
#define NN      50000
#define EE      800000
#define FIN     256
#define HH      4
#define DD      32
#define HD      128     // HH*DD
#define NEG_SLOPE 0.2f
#define BUCKET  64      // per-dst edge slot capacity (P(deg>64) ~ e^-50)

typedef unsigned int u32;
typedef unsigned long long u64;

// -------- scratch (no allocations allowed) --------
// NOTE (R11 learning): do NOT zero g_cnt inside gat_kernel — that variant
// measured +27us on the gat kernel across two rounds. Dedicated init kernel.
__device__ float g_ft[NN * HD];          // projected features fp32 [N, H*D]
__device__ float g_el[NN * HH];          // left logits  [N, H]
__device__ float g_er[NN * HH];          // right logits [N, H]
__device__ int   g_cnt[NN];              // per-dst degree counter
__device__ int   g_esrc[NN * BUCKET];    // src node per edge, bucketed by dst

// ============================================================
// helpers
// ============================================================
__device__ __forceinline__ float to_tf32(float x) {
    u32 o;
    asm("cvt.rna.tf32.f32 %0, %1;" : "=r"(o) : "f"(x));
    return __uint_as_float(o);
}

__device__ __forceinline__ void mma_tf32(float* d, const u32* a,
                                         u32 b0, u32 b1) {
    asm volatile(
        "mma.sync.aligned.m16n8k8.row.col.f32.tf32.tf32.f32 "
        "{%0,%1,%2,%3}, {%4,%5,%6,%7}, {%8,%9}, {%0,%1,%2,%3};\n"
        : "+f"(d[0]), "+f"(d[1]), "+f"(d[2]), "+f"(d[3])
        : "r"(a[0]), "r"(a[1]), "r"(a[2]), "r"(a[3]), "r"(b0), "r"(b1));
}

__device__ __forceinline__ void cp16(void* s, const void* g, bool pred) {
    u32 sa = (u32)__cvta_generic_to_shared(s);
    int sz = pred ? 16 : 0;
    asm volatile("cp.async.cg.shared.global [%0], [%1], 16, %2;\n"
                 :: "r"(sa), "l"(g), "r"(sz));
}
__device__ __forceinline__ void cp_commit() {
    asm volatile("cp.async.commit_group;\n" ::: "memory");
}

// ============================================================
// 1. GEMM: ft[N,128] = feat[N,256] @ W[256,128]  (tf32 tensor core)
//    BM=128, BN=128, BK=32, 8 warps, cp.async 2-stage (measured 36.3us).
//    Epilogue: fp32 ft store + fused fp32 el/er logits.
// ============================================================
#define A_PITCH 36
#define B_PITCH 132
#define A_TILE  (128 * A_PITCH)
#define B_TILE  (32 * B_PITCH)
#define GEMM_SMEM_BYTES ((2 * A_TILE + 2 * B_TILE) * 4)

__global__ __launch_bounds__(256) void gemm_tc(
    const float* __restrict__ feat, const float* __restrict__ W,
    const float* __restrict__ attn_l, const float* __restrict__ attn_r)
{
    extern __shared__ float sm[];
    float* As = sm;                 // [2][128][A_PITCH]
    float* Bs = sm + 2 * A_TILE;    // [2][32][B_PITCH]

    const int tid  = threadIdx.x;
    const int lane = tid & 31;
    const int warp = tid >> 5;
    const int wm = (warp >> 1) * 32;
    const int wn = (warp & 1) * 64;
    const int g  = lane >> 2;
    const int tg = lane & 3;
    const int row0 = blockIdx.x * 128;

    float acc[2][8][4];
#pragma unroll
    for (int mi = 0; mi < 2; mi++)
#pragma unroll
        for (int ni = 0; ni < 8; ni++)
#pragma unroll
            for (int j = 0; j < 4; j++) acc[mi][ni][j] = 0.f;

    auto load_tile = [&](int stage, int k0) {
        float* A = As + stage * A_TILE;
        float* B = Bs + stage * B_TILE;
#pragma unroll
        for (int i = 0; i < 4; i++) {
            int idx = tid + i * 256;
            int r = idx >> 3, c = (idx & 7) * 4;
            bool p = (row0 + r) < NN;
            cp16(&A[r * A_PITCH + c], &feat[(size_t)(row0 + r) * FIN + k0 + c], p);
        }
#pragma unroll
        for (int i = 0; i < 4; i++) {
            int idx = tid + i * 256;
            int r = idx >> 5, c = (idx & 31) * 4;
            cp16(&B[r * B_PITCH + c], &W[(k0 + r) * HD + c], true);
        }
        cp_commit();
    };

    load_tile(0, 0);

    for (int kt = 0; kt < 8; kt++) {
        int cur = kt & 1;
        if (kt < 7) {
            load_tile(cur ^ 1, (kt + 1) * 32);
            asm volatile("cp.async.wait_group %0;\n" :: "n"(1) : "memory");
        } else {
            asm volatile("cp.async.wait_group %0;\n" :: "n"(0) : "memory");
        }
        __syncthreads();

        const float* A = As + cur * A_TILE;
        const float* B = Bs + cur * B_TILE;
#pragma unroll
        for (int kf = 0; kf < 4; kf++) {
            int kb = kf * 8;
            u32 a[2][4];
#pragma unroll
            for (int mi = 0; mi < 2; mi++) {
                int rb = wm + mi * 16;
                a[mi][0] = __float_as_uint(to_tf32(A[(rb + g    ) * A_PITCH + kb + tg    ]));
                a[mi][1] = __float_as_uint(to_tf32(A[(rb + g + 8) * A_PITCH + kb + tg    ]));
                a[mi][2] = __float_as_uint(to_tf32(A[(rb + g    ) * A_PITCH + kb + tg + 4]));
                a[mi][3] = __float_as_uint(to_tf32(A[(rb + g + 8) * A_PITCH + kb + tg + 4]));
            }
#pragma unroll
            for (int ni = 0; ni < 8; ni++) {
                u32 b0 = __float_as_uint(to_tf32(B[(kb + tg    ) * B_PITCH + wn + ni * 8 + g]));
                u32 b1 = __float_as_uint(to_tf32(B[(kb + tg + 4) * B_PITCH + wn + ni * 8 + g]));
                mma_tf32(acc[0][ni], a[0], b0, b1);
                mma_tf32(acc[1][ni], a[1], b0, b1);
            }
        }
        __syncthreads();
    }

    // ---- epilogue part 1: fp32 ft store ----
#pragma unroll
    for (int mi = 0; mi < 2; mi++) {
        int r = row0 + wm + mi * 16 + g;
#pragma unroll
        for (int ni = 0; ni < 8; ni++) {
            int c = wn + ni * 8 + 2 * tg;
            if (r < NN)
                *(float2*)&g_ft[(size_t)r * HD + c] = make_float2(acc[mi][ni][0], acc[mi][ni][1]);
            if (r + 8 < NN)
                *(float2*)&g_ft[(size_t)(r + 8) * HD + c] = make_float2(acc[mi][ni][2], acc[mi][ni][3]);
        }
    }

    // ---- epilogue part 2: fused fp32 logits ----
    float alv[8][2], arv[8][2];
#pragma unroll
    for (int ni = 0; ni < 8; ni++) {
        int c = wn + ni * 8 + 2 * tg;
        alv[ni][0] = attn_l[c];     alv[ni][1] = attn_l[c + 1];
        arv[ni][0] = attn_r[c];     arv[ni][1] = attn_r[c + 1];
    }
#pragma unroll
    for (int mi = 0; mi < 2; mi++) {
        int r = row0 + wm + mi * 16 + g;
#pragma unroll
        for (int half = 0; half < 2; half++) {
            float el_lo = 0.f, er_lo = 0.f, el_hi = 0.f, er_hi = 0.f;
#pragma unroll
            for (int k = 0; k < 4; k++) {
                int ni = half * 4 + k;
                el_lo += acc[mi][ni][0] * alv[ni][0] + acc[mi][ni][1] * alv[ni][1];
                er_lo += acc[mi][ni][0] * arv[ni][0] + acc[mi][ni][1] * arv[ni][1];
                el_hi += acc[mi][ni][2] * alv[ni][0] + acc[mi][ni][3] * alv[ni][1];
                er_hi += acc[mi][ni][2] * arv[ni][0] + acc[mi][ni][3] * arv[ni][1];
            }
#pragma unroll
            for (int off = 1; off < 4; off <<= 1) {
                el_lo += __shfl_xor_sync(0xffffffffu, el_lo, off);
                er_lo += __shfl_xor_sync(0xffffffffu, er_lo, off);
                el_hi += __shfl_xor_sync(0xffffffffu, el_hi, off);
                er_hi += __shfl_xor_sync(0xffffffffu, er_hi, off);
            }
            if (tg == 0) {
                int h = (wn >> 5) + half;
                if (r < NN) {
                    g_el[r * HH + h] = el_lo;
                    g_er[r * HH + h] = er_lo;
                }
                if (r + 8 < NN) {
                    g_el[(r + 8) * HH + h] = el_hi;
                    g_er[(r + 8) * HH + h] = er_hi;
                }
            }
        }
    }
}

// ============================================================
// 2. counter init + bucketed edge scatter
// ============================================================
__global__ void init_cnt_kernel()
{
    int i = blockIdx.x * blockDim.x + threadIdx.x;
    if (i < NN / 4) ((int4*)g_cnt)[i] = make_int4(0, 0, 0, 0);
}

__global__ void scatter_kernel(const int* __restrict__ src, const int* __restrict__ dst)
{
    int e = blockIdx.x * blockDim.x + threadIdx.x;
    if (e >= EE) return;
    int s = __ldg(&src[e]);
    int d = __ldg(&dst[e]);
    int p = atomicAdd(&g_cnt[d], 1);
    if (p < BUCKET) g_esrc[d * BUCKET + p] = s;
}

// ============================================================
// 3. warp-per-dst-node GAT: two-phase softmax; pass B with
//    depth-2 rotating prefetch (bounded register cost).
// ============================================================
__device__ __forceinline__ float leaky(float x) {
    return (x > 0.f) ? x : NEG_SLOPE * x;
}

__global__ __launch_bounds__(256) void gat_kernel(
    const float* __restrict__ bias, float* __restrict__ out)
{
    __shared__ float2 swe[8][HH][BUCKET];   // 16 KB

    int v = (blockIdx.x * blockDim.x + threadIdx.x) >> 5;
    int lane = threadIdx.x & 31;
    int wrp  = threadIdx.x >> 5;
    if (v >= NN) return;
    float2 (*we)[BUCKET] = swe[wrp];

    int deg = min(g_cnt[v], BUCKET);
    int beg = v * BUCKET;

    float4 b = *(const float4*)&bias[lane * 4];

    if (deg == 0) {
        *(float4*)&out[(size_t)v * HD + lane * 4] = b;
        return;
    }

    float4 er4 = *(const float4*)&g_er[v * HH];

    // ---- pass A: stage {u, leaky logit} per (edge, head); per-head max ----
    float m[4] = { -CUDART_INF_F, -CUDART_INF_F, -CUDART_INF_F, -CUDART_INF_F };

    for (int i = lane; i < deg; i += 32) {
        int u = g_esrc[beg + i];
        float4 el4 = *(const float4*)&g_el[u * HH];
        float ub = __int_as_float(u);
        float x0 = leaky(el4.x + er4.x);
        float x1 = leaky(el4.y + er4.y);
        float x2 = leaky(el4.z + er4.z);
        float x3 = leaky(el4.w + er4.w);
        we[0][i] = make_float2(ub, x0);
        we[1][i] = make_float2(ub, x1);
        we[2][i] = make_float2(ub, x2);
        we[3][i] = make_float2(ub, x3);
        m[0] = fmaxf(m[0], x0);
        m[1] = fmaxf(m[1], x1);
        m[2] = fmaxf(m[2], x2);
        m[3] = fmaxf(m[3], x3);
    }

    // ---- warp max merge ----
#pragma unroll
    for (int off = 16; off; off >>= 1) {
#pragma unroll
        for (int h = 0; h < 4; h++)
            m[h] = fmaxf(m[h], __shfl_xor_sync(0xffffffffu, m[h], off));
    }
    __syncwarp();

    // ---- weight phase (head-major): e = exp(x - m[h]); 8-lane group sums ----
    int h  = lane >> 3;
    int i0 = lane & 7;
    float mh = m[h];
    float sloc = 0.f;
    for (int i = i0; i < deg; i += 8) {
        float x = we[h][i].y;
        float a = __expf(x - mh);
        we[h][i].y = a;
        sloc += a;
    }
#pragma unroll
    for (int off = 1; off < 8; off <<= 1)
        sloc += __shfl_xor_sync(0xffffffffu, sloc, off);
    float inv = 1.f / sloc;
    __syncwarp();

    // ---- pass B: depth-2 rotating prefetch gather-accumulate ----
    u64 accA = 0ull, accB = 0ull;
    const char* ftbase = (const char*)g_ft + (size_t)lane * 16;

    float2 pc = we[h][0];
    ulonglong2 fc = *(const ulonglong2*)(ftbase + (size_t)__float_as_int(pc.x) * (HD * 4));
#pragma unroll 4
    for (int i = 1; i < deg; i++) {
        float2 pn = we[h][i];
        ulonglong2 fn = *(const ulonglong2*)(ftbase + (size_t)__float_as_int(pn.x) * (HD * 4));
        u64 aa;
        asm("mov.b64 %0, {%1, %1};" : "=l"(aa) : "r"(__float_as_uint(pc.y)));
        asm("fma.rn.f32x2 %0, %1, %2, %0;" : "+l"(accA) : "l"(fc.x), "l"(aa));
        asm("fma.rn.f32x2 %0, %1, %2, %0;" : "+l"(accB) : "l"(fc.y), "l"(aa));
        pc = pn; fc = fn;
    }
    {
        u64 aa;
        asm("mov.b64 %0, {%1, %1};" : "=l"(aa) : "r"(__float_as_uint(pc.y)));
        asm("fma.rn.f32x2 %0, %1, %2, %0;" : "+l"(accA) : "l"(fc.x), "l"(aa));
        asm("fma.rn.f32x2 %0, %1, %2, %0;" : "+l"(accB) : "l"(fc.y), "l"(aa));
    }

    u32 a0, a1, a2, a3;
    asm("mov.b64 {%0, %1}, %2;" : "=r"(a0), "=r"(a1) : "l"(accA));
    asm("mov.b64 {%0, %1}, %2;" : "=r"(a2), "=r"(a3) : "l"(accB));
    float4 r;
    r.x = fmaf(__uint_as_float(a0), inv, b.x);
    r.y = fmaf(__uint_as_float(a1), inv, b.y);
    r.z = fmaf(__uint_as_float(a2), inv, b.z);
    r.w = fmaf(__uint_as_float(a3), inv, b.w);
    *(float4*)&out[(size_t)v * HD + lane * 4] = r;
}

// ============================================================
extern "C" void kernel_launch(void* const* d_in, const int* in_sizes, int n_in,
                              void* d_out, int out_size)
{
    const float* feat   = (const float*)d_in[0];
    const int*   src    = (const int*)  d_in[1];
    const int*   dst    = (const int*)  d_in[2];
    const float* W      = (const float*)d_in[3];
    const float* attn_l = (const float*)d_in[4];
    const float* attn_r = (const float*)d_in[5];
    const float* bias   = (const float*)d_in[6];
    float* out = (float*)d_out;

    cudaFuncSetAttribute(gemm_tc, cudaFuncAttributeMaxDynamicSharedMemorySize,
                         GEMM_SMEM_BYTES);

    // projection + fused fp32 logits (tf32 tensor core, cp.async pipelined)
    gemm_tc<<<(NN + 127) / 128, 256, GEMM_SMEM_BYTES>>>(feat, W, attn_l, attn_r);

    // bucketed CSR build (dedicated init kernel — see R11 note)
    init_cnt_kernel<<<(NN / 4 + 255) / 256, 256>>>();
    scatter_kernel<<<(EE + 255) / 256, 256>>>(src, dst);

    // softmax + SpMM
    gat_kernel<<<(NN * 32 + 255) / 256, 256>>>(bias, out);
}

// round 13
// speedup vs baseline: 1.3419x; 1.0017x over previous
#include <cuda_runtime.h>
#include <math_constants.h>
#include <cstdint>

// Problem constants
#define NN      50000
#define EE      800000
#define FIN     256
#define HH      4
#define DD      32
#define HD      128     // HH*DD
#define NEG_SLOPE 0.2f
#define BUCKET  64      // per-dst edge slot capacity (P(deg>64) ~ e^-50)

typedef unsigned int u32;
typedef unsigned long long u64;

// -------- scratch (no allocations allowed) --------
// NOTE (R11 learning): do NOT zero g_cnt inside gat_kernel — that variant
// measured +27us on the gat kernel across two rounds. Dedicated init kernel.
__device__ float g_ft[NN * HD];          // projected features fp32 [N, H*D]
__device__ float g_el[NN * HH];          // left logits  [N, H]
__device__ float g_er[NN * HH];          // right logits [N, H]
__device__ int   g_cnt[NN];              // per-dst degree counter
__device__ int   g_esrc[NN * BUCKET];    // src node per edge, bucketed by dst

// ============================================================
// helpers
// ============================================================
__device__ __forceinline__ float to_tf32(float x) {
    u32 o;
    asm("cvt.rna.tf32.f32 %0, %1;" : "=r"(o) : "f"(x));
    return __uint_as_float(o);
}

__device__ __forceinline__ void mma_tf32(float* d, const u32* a,
                                         u32 b0, u32 b1) {
    asm volatile(
        "mma.sync.aligned.m16n8k8.row.col.f32.tf32.tf32.f32 "
        "{%0,%1,%2,%3}, {%4,%5,%6,%7}, {%8,%9}, {%0,%1,%2,%3};\n"
        : "+f"(d[0]), "+f"(d[1]), "+f"(d[2]), "+f"(d[3])
        : "r"(a[0]), "r"(a[1]), "r"(a[2]), "r"(a[3]), "r"(b0), "r"(b1));
}

__device__ __forceinline__ void cp16(void* s, const void* g, bool pred) {
    u32 sa = (u32)__cvta_generic_to_shared(s);
    int sz = pred ? 16 : 0;
    asm volatile("cp.async.cg.shared.global [%0], [%1], 16, %2;\n"
                 :: "r"(sa), "l"(g), "r"(sz));
}
__device__ __forceinline__ void cp_commit() {
    asm volatile("cp.async.commit_group;\n" ::: "memory");
}

// ============================================================
// 1. GEMM: ft[N,128] = feat[N,256] @ W[256,128]  (tf32 tensor core)
//    BM=128, BN=128, BK=32, 8 warps, cp.async 2-stage (measured 36.3us).
//    Epilogue: fp32 ft store + fused fp32 el/er logits.
// ============================================================
#define A_PITCH 36
#define B_PITCH 132
#define A_TILE  (128 * A_PITCH)
#define B_TILE  (32 * B_PITCH)
#define GEMM_SMEM_BYTES ((2 * A_TILE + 2 * B_TILE) * 4)

__global__ __launch_bounds__(256) void gemm_tc(
    const float* __restrict__ feat, const float* __restrict__ W,
    const float* __restrict__ attn_l, const float* __restrict__ attn_r)
{
    extern __shared__ float sm[];
    float* As = sm;                 // [2][128][A_PITCH]
    float* Bs = sm + 2 * A_TILE;    // [2][32][B_PITCH]

    const int tid  = threadIdx.x;
    const int lane = tid & 31;
    const int warp = tid >> 5;
    const int wm = (warp >> 1) * 32;
    const int wn = (warp & 1) * 64;
    const int g  = lane >> 2;
    const int tg = lane & 3;
    const int row0 = blockIdx.x * 128;

    float acc[2][8][4];
#pragma unroll
    for (int mi = 0; mi < 2; mi++)
#pragma unroll
        for (int ni = 0; ni < 8; ni++)
#pragma unroll
            for (int j = 0; j < 4; j++) acc[mi][ni][j] = 0.f;

    auto load_tile = [&](int stage, int k0) {
        float* A = As + stage * A_TILE;
        float* B = Bs + stage * B_TILE;
#pragma unroll
        for (int i = 0; i < 4; i++) {
            int idx = tid + i * 256;
            int r = idx >> 3, c = (idx & 7) * 4;
            bool p = (row0 + r) < NN;
            cp16(&A[r * A_PITCH + c], &feat[(size_t)(row0 + r) * FIN + k0 + c], p);
        }
#pragma unroll
        for (int i = 0; i < 4; i++) {
            int idx = tid + i * 256;
            int r = idx >> 5, c = (idx & 31) * 4;
            cp16(&B[r * B_PITCH + c], &W[(k0 + r) * HD + c], true);
        }
        cp_commit();
    };

    load_tile(0, 0);

    for (int kt = 0; kt < 8; kt++) {
        int cur = kt & 1;
        if (kt < 7) {
            load_tile(cur ^ 1, (kt + 1) * 32);
            asm volatile("cp.async.wait_group %0;\n" :: "n"(1) : "memory");
        } else {
            asm volatile("cp.async.wait_group %0;\n" :: "n"(0) : "memory");
        }
        __syncthreads();

        const float* A = As + cur * A_TILE;
        const float* B = Bs + cur * B_TILE;
#pragma unroll
        for (int kf = 0; kf < 4; kf++) {
            int kb = kf * 8;
            u32 a[2][4];
#pragma unroll
            for (int mi = 0; mi < 2; mi++) {
                int rb = wm + mi * 16;
                a[mi][0] = __float_as_uint(to_tf32(A[(rb + g    ) * A_PITCH + kb + tg    ]));
                a[mi][1] = __float_as_uint(to_tf32(A[(rb + g + 8) * A_PITCH + kb + tg    ]));
                a[mi][2] = __float_as_uint(to_tf32(A[(rb + g    ) * A_PITCH + kb + tg + 4]));
                a[mi][3] = __float_as_uint(to_tf32(A[(rb + g + 8) * A_PITCH + kb + tg + 4]));
            }
#pragma unroll
            for (int ni = 0; ni < 8; ni++) {
                u32 b0 = __float_as_uint(to_tf32(B[(kb + tg    ) * B_PITCH + wn + ni * 8 + g]));
                u32 b1 = __float_as_uint(to_tf32(B[(kb + tg + 4) * B_PITCH + wn + ni * 8 + g]));
                mma_tf32(acc[0][ni], a[0], b0, b1);
                mma_tf32(acc[1][ni], a[1], b0, b1);
            }
        }
        __syncthreads();
    }

    // ---- epilogue part 1: fp32 ft store ----
#pragma unroll
    for (int mi = 0; mi < 2; mi++) {
        int r = row0 + wm + mi * 16 + g;
#pragma unroll
        for (int ni = 0; ni < 8; ni++) {
            int c = wn + ni * 8 + 2 * tg;
            if (r < NN)
                *(float2*)&g_ft[(size_t)r * HD + c] = make_float2(acc[mi][ni][0], acc[mi][ni][1]);
            if (r + 8 < NN)
                *(float2*)&g_ft[(size_t)(r + 8) * HD + c] = make_float2(acc[mi][ni][2], acc[mi][ni][3]);
        }
    }

    // ---- epilogue part 2: fused fp32 logits ----
    float alv[8][2], arv[8][2];
#pragma unroll
    for (int ni = 0; ni < 8; ni++) {
        int c = wn + ni * 8 + 2 * tg;
        alv[ni][0] = attn_l[c];     alv[ni][1] = attn_l[c + 1];
        arv[ni][0] = attn_r[c];     arv[ni][1] = attn_r[c + 1];
    }
#pragma unroll
    for (int mi = 0; mi < 2; mi++) {
        int r = row0 + wm + mi * 16 + g;
#pragma unroll
        for (int half = 0; half < 2; half++) {
            float el_lo = 0.f, er_lo = 0.f, el_hi = 0.f, er_hi = 0.f;
#pragma unroll
            for (int k = 0; k < 4; k++) {
                int ni = half * 4 + k;
                el_lo += acc[mi][ni][0] * alv[ni][0] + acc[mi][ni][1] * alv[ni][1];
                er_lo += acc[mi][ni][0] * arv[ni][0] + acc[mi][ni][1] * arv[ni][1];
                el_hi += acc[mi][ni][2] * alv[ni][0] + acc[mi][ni][3] * alv[ni][1];
                er_hi += acc[mi][ni][2] * arv[ni][0] + acc[mi][ni][3] * arv[ni][1];
            }
#pragma unroll
            for (int off = 1; off < 4; off <<= 1) {
                el_lo += __shfl_xor_sync(0xffffffffu, el_lo, off);
                er_lo += __shfl_xor_sync(0xffffffffu, er_lo, off);
                el_hi += __shfl_xor_sync(0xffffffffu, el_hi, off);
                er_hi += __shfl_xor_sync(0xffffffffu, er_hi, off);
            }
            if (tg == 0) {
                int h = (wn >> 5) + half;
                if (r < NN) {
                    g_el[r * HH + h] = el_lo;
                    g_er[r * HH + h] = er_lo;
                }
                if (r + 8 < NN) {
                    g_el[(r + 8) * HH + h] = el_hi;
                    g_er[(r + 8) * HH + h] = er_hi;
                }
            }
        }
    }
}

// ============================================================
// 2. counter init + bucketed edge scatter
// ============================================================
__global__ void init_cnt_kernel()
{
    int i = blockIdx.x * blockDim.x + threadIdx.x;
    if (i < NN / 4) ((int4*)g_cnt)[i] = make_int4(0, 0, 0, 0);
}

__global__ void scatter_kernel(const int* __restrict__ src, const int* __restrict__ dst)
{
    int e = blockIdx.x * blockDim.x + threadIdx.x;
    if (e >= EE) return;
    int s = __ldg(&src[e]);
    int d = __ldg(&dst[e]);
    int p = atomicAdd(&g_cnt[d], 1);
    if (p < BUCKET) g_esrc[d * BUCKET + p] = s;
}

// ============================================================
// 3. warp-per-dst-node GAT: two-phase softmax; pass B with
//    depth-2 rotating prefetch (bounded register cost).
// ============================================================
__device__ __forceinline__ float leaky(float x) {
    return (x > 0.f) ? x : NEG_SLOPE * x;
}

__global__ __launch_bounds__(256) void gat_kernel(
    const float* __restrict__ bias, float* __restrict__ out)
{
    __shared__ float2 swe[8][HH][BUCKET];   // 16 KB

    int v = (blockIdx.x * blockDim.x + threadIdx.x) >> 5;
    int lane = threadIdx.x & 31;
    int wrp  = threadIdx.x >> 5;
    if (v >= NN) return;
    float2 (*we)[BUCKET] = swe[wrp];

    int deg = min(g_cnt[v], BUCKET);
    int beg = v * BUCKET;

    float4 b = *(const float4*)&bias[lane * 4];

    if (deg == 0) {
        *(float4*)&out[(size_t)v * HD + lane * 4] = b;
        return;
    }

    float4 er4 = *(const float4*)&g_er[v * HH];

    // ---- pass A: stage {u, leaky logit} per (edge, head); per-head max ----
    float m[4] = { -CUDART_INF_F, -CUDART_INF_F, -CUDART_INF_F, -CUDART_INF_F };

    for (int i = lane; i < deg; i += 32) {
        int u = g_esrc[beg + i];
        float4 el4 = *(const float4*)&g_el[u * HH];
        float ub = __int_as_float(u);
        float x0 = leaky(el4.x + er4.x);
        float x1 = leaky(el4.y + er4.y);
        float x2 = leaky(el4.z + er4.z);
        float x3 = leaky(el4.w + er4.w);
        we[0][i] = make_float2(ub, x0);
        we[1][i] = make_float2(ub, x1);
        we[2][i] = make_float2(ub, x2);
        we[3][i] = make_float2(ub, x3);
        m[0] = fmaxf(m[0], x0);
        m[1] = fmaxf(m[1], x1);
        m[2] = fmaxf(m[2], x2);
        m[3] = fmaxf(m[3], x3);
    }

    // ---- warp max merge ----
#pragma unroll
    for (int off = 16; off; off >>= 1) {
#pragma unroll
        for (int h = 0; h < 4; h++)
            m[h] = fmaxf(m[h], __shfl_xor_sync(0xffffffffu, m[h], off));
    }
    __syncwarp();

    // ---- weight phase (head-major): e = exp(x - m[h]); 8-lane group sums ----
    int h  = lane >> 3;
    int i0 = lane & 7;
    float mh = m[h];
    float sloc = 0.f;
    for (int i = i0; i < deg; i += 8) {
        float x = we[h][i].y;
        float a = __expf(x - mh);
        we[h][i].y = a;
        sloc += a;
    }
#pragma unroll
    for (int off = 1; off < 8; off <<= 1)
        sloc += __shfl_xor_sync(0xffffffffu, sloc, off);
    float inv = 1.f / sloc;
    __syncwarp();

    // ---- pass B: depth-2 rotating prefetch gather-accumulate ----
    u64 accA = 0ull, accB = 0ull;
    const char* ftbase = (const char*)g_ft + (size_t)lane * 16;

    float2 pc = we[h][0];
    ulonglong2 fc = *(const ulonglong2*)(ftbase + (size_t)__float_as_int(pc.x) * (HD * 4));
#pragma unroll 4
    for (int i = 1; i < deg; i++) {
        float2 pn = we[h][i];
        ulonglong2 fn = *(const ulonglong2*)(ftbase + (size_t)__float_as_int(pn.x) * (HD * 4));
        u64 aa;
        asm("mov.b64 %0, {%1, %1};" : "=l"(aa) : "r"(__float_as_uint(pc.y)));
        asm("fma.rn.f32x2 %0, %1, %2, %0;" : "+l"(accA) : "l"(fc.x), "l"(aa));
        asm("fma.rn.f32x2 %0, %1, %2, %0;" : "+l"(accB) : "l"(fc.y), "l"(aa));
        pc = pn; fc = fn;
    }
    {
        u64 aa;
        asm("mov.b64 %0, {%1, %1};" : "=l"(aa) : "r"(__float_as_uint(pc.y)));
        asm("fma.rn.f32x2 %0, %1, %2, %0;" : "+l"(accA) : "l"(fc.x), "l"(aa));
        asm("fma.rn.f32x2 %0, %1, %2, %0;" : "+l"(accB) : "l"(fc.y), "l"(aa));
    }

    u32 a0, a1, a2, a3;
    asm("mov.b64 {%0, %1}, %2;" : "=r"(a0), "=r"(a1) : "l"(accA));
    asm("mov.b64 {%0, %1}, %2;" : "=r"(a2), "=r"(a3) : "l"(accB));
    float4 r;
    r.x = fmaf(__uint_as_float(a0), inv, b.x);
    r.y = fmaf(__uint_as_float(a1), inv, b.y);
    r.z = fmaf(__uint_as_float(a2), inv, b.z);
    r.w = fmaf(__uint_as_float(a3), inv, b.w);
    *(float4*)&out[(size_t)v * HD + lane * 4] = r;
}

// ============================================================
extern "C" void kernel_launch(void* const* d_in, const int* in_sizes, int n_in,
                              void* d_out, int out_size)
{
    const float* feat   = (const float*)d_in[0];
    const int*   src    = (const int*)  d_in[1];
    const int*   dst    = (const int*)  d_in[2];
    const float* W      = (const float*)d_in[3];
    const float* attn_l = (const float*)d_in[4];
    const float* attn_r = (const float*)d_in[5];
    const float* bias   = (const float*)d_in[6];
    float* out = (float*)d_out;

    cudaFuncSetAttribute(gemm_tc, cudaFuncAttributeMaxDynamicSharedMemorySize,
                         GEMM_SMEM_BYTES);

    // projection + fused fp32 logits (tf32 tensor core, cp.async pipelined)
    gemm_tc<<<(NN + 127) / 128, 256, GEMM_SMEM_BYTES>>>(feat, W, attn_l, attn_r);

    // bucketed CSR build (dedicated init kernel — see R11 note)
    init_cnt_kernel<<<(NN / 4 + 255) / 256, 256>>>();
    scatter_kernel<<<(EE + 255) / 256, 256>>>(src, dst);

    // softmax + SpMM
    gat_kernel<<<(NN * 32 + 255) / 256, 256>>>(bias, out);
}